// round 8
// baseline (speedup 1.0000x reference)
#include <cuda_runtime.h>
#include <math.h>

#define N_OBS   256
#define N_Y     128
#define N_X     64
#define NITERS  150
#define NTHREADS 512
#define NWARPS   16
#define EP_STRIDE 132   // row-major ep stride: 528B/row

__device__ float g_ep[N_OBS * N_Y];             // ep row-major [t][j]
__device__ float g_yhat_fallback[N_OBS * N_Y];

struct SolverSmem {
    float ep[N_OBS * EP_STRIDE];                // 135168 B, row-major padded
    float zA[N_Y],  zB[N_Y];
    float yhA[N_Y], yhB[N_Y];
    float wA[N_OBS], wB[N_OBS];
    float partA[4 * N_Y], partB[4 * N_Y];       // 4 t-quarters per j
    float redIA[NWARPS], redWA[NWARPS], redIB[NWARPS], redWB[NWARPS];
    float cA, etaA, lamA;
    float cB, etaB, lamB;
};

// ---- packed f32x2 helpers (sm_103a) ---------------------------------------
__device__ __forceinline__ void fma2(unsigned long long& d,
                                     unsigned long long a,
                                     unsigned long long b) {
    asm("fma.rn.f32x2 %0, %1, %2, %0;" : "+l"(d) : "l"(a), "l"(b));
}
__device__ __forceinline__ unsigned long long pk2(float lo, float hi) {
    unsigned long long r;
    asm("mov.b64 %0, {%1, %2};" : "=l"(r) : "f"(lo), "f"(hi));
    return r;
}
__device__ __forceinline__ float upk_sum(unsigned long long v) {
    float lo, hi;
    asm("mov.b64 {%0, %1}, %2;" : "=f"(lo), "=f"(hi) : "l"(v));
    return lo + hi;
}

// ---------------------------------------------------------------------------
// Kernel 1: Y_hat = X @ W^T + b ; ep = Y - Y_hat (row-major)
// ---------------------------------------------------------------------------
__global__ void prep_kernel(const float* __restrict__ X,
                            const float* __restrict__ Y,
                            const float* __restrict__ W,
                            const float* __restrict__ b,
                            float* __restrict__ yhat_out) {
    __shared__ float Xs[N_X];
    __shared__ float Ws[N_Y * (N_X + 1)];
    const int t = blockIdx.x;
    const int i = threadIdx.x;

    if (i < N_X) Xs[i] = X[t * N_X + i];
    for (int idx = i; idx < N_Y * N_X; idx += blockDim.x) {
        int r = idx >> 6, cx = idx & 63;
        Ws[r * (N_X + 1) + cx] = W[idx];
    }
    __syncthreads();

    float acc = b[i];
#pragma unroll
    for (int x = 0; x < N_X; x++) acc += Xs[x] * Ws[i * (N_X + 1) + x];

    yhat_out[t * N_Y + i] = acc;
    g_ep[t * N_Y + i] = Y[t * N_Y + i] - acc;
}

// ---------------------------------------------------------------------------
// Block-layout warp-local simplex projection of 128 values (i = lane*4 + r).
// part has 4 t-quarter segments of 128.
// ---------------------------------------------------------------------------
__device__ __forceinline__ void cswap(float& a, float& b, bool asc) {
    const float lo = fminf(a, b), hi = fmaxf(a, b);
    a = asc ? lo : hi;
    b = asc ? hi : lo;
}

__device__ __forceinline__ void project_warp_blk(const float* __restrict__ part,
                                                 const float* __restrict__ yh,
                                                 float* __restrict__ zz,
                                                 float lr, float gamma) {
    const unsigned FULL = 0xffffffffu;
    const int lane = threadIdx.x & 31;

    const float4 p0 = *reinterpret_cast<const float4*>(&part[lane * 4]);
    const float4 p1 = *reinterpret_cast<const float4*>(&part[128 + lane * 4]);
    const float4 p2 = *reinterpret_cast<const float4*>(&part[256 + lane * 4]);
    const float4 p3 = *reinterpret_cast<const float4*>(&part[384 + lane * 4]);
    const float4 yv = *reinterpret_cast<const float4*>(&yh[lane * 4]);
    const float4 zv = *reinterpret_cast<const float4*>(&zz[lane * 4]);

    float vorig[4], val[4];
    vorig[0] = zv.x - lr * (p0.x + p1.x + p2.x + p3.x - gamma * yv.x);
    vorig[1] = zv.y - lr * (p0.y + p1.y + p2.y + p3.y - gamma * yv.y);
    vorig[2] = zv.z - lr * (p0.z + p1.z + p2.z + p3.z - gamma * yv.z);
    vorig[3] = zv.w - lr * (p0.w + p1.w + p2.w + p3.w - gamma * yv.w);
#pragma unroll
    for (int r = 0; r < 4; r++) val[r] = vorig[r];

    // ---- bitonic ascending sort over i = lane*4 + r ----
    cswap(val[0], val[1], true);
    cswap(val[2], val[3], false);
    {
        const bool a = (lane & 1) == 0;
        cswap(val[0], val[2], a); cswap(val[1], val[3], a);
        cswap(val[0], val[1], a); cswap(val[2], val[3], a);
    }

#define SHFL_LEVEL(ls, asc) do {                                         \
        const bool _low = (lane & (ls)) == 0;                            \
        _Pragma("unroll")                                                \
        for (int r = 0; r < 4; r++) {                                    \
            const float pv = __shfl_xor_sync(FULL, val[r], (ls));        \
            val[r] = (_low == (asc)) ? fminf(val[r], pv)                 \
                                     : fmaxf(val[r], pv);                \
        }                                                                \
    } while (0)

#define REG_TAIL(asc) do {                                               \
        cswap(val[0], val[2], (asc)); cswap(val[1], val[3], (asc));      \
        cswap(val[0], val[1], (asc)); cswap(val[2], val[3], (asc));      \
    } while (0)

    { const bool a = (lane & 2)  == 0; SHFL_LEVEL(1, a); REG_TAIL(a); }
    { const bool a = (lane & 4)  == 0; SHFL_LEVEL(2, a); SHFL_LEVEL(1, a); REG_TAIL(a); }
    { const bool a = (lane & 8)  == 0; SHFL_LEVEL(4, a); SHFL_LEVEL(2, a); SHFL_LEVEL(1, a); REG_TAIL(a);}
    { const bool a = (lane & 16) == 0; SHFL_LEVEL(8, a); SHFL_LEVEL(4, a); SHFL_LEVEL(2, a);
      SHFL_LEVEL(1, a); REG_TAIL(a); }
    { SHFL_LEVEL(16, true); SHFL_LEVEL(8, true); SHFL_LEVEL(4, true); SHFL_LEVEL(2, true);
      SHFL_LEVEL(1, true); REG_TAIL(true); }

#undef SHFL_LEVEL
#undef REG_TAIL

    // ---- inclusive prefix sum over sorted values ----
    const float s0 = val[0];
    const float s1 = s0 + val[1];
    const float s2 = s1 + val[2];
    const float s3 = s2 + val[3];
    float incl = s3;
#pragma unroll
    for (int d = 1; d < 32; d <<= 1) {
        const float y = __shfl_up_sync(FULL, incl, d);
        if (lane >= d) incl += y;
    }
    const float prefix = incl - s3;
    const float Stot = __shfl_sync(FULL, incl, 31);
    const float P[4] = { s0 + prefix, s1 + prefix, s2 + prefix, s3 + prefix };

    int rho = 0;
    float cssr[4];
#pragma unroll
    for (int r = 0; r < 4; r++) {
        const int i = lane * 4 + r;
        const float css = Stot - P[r] + val[r];
        cssr[r] = css;
        const bool cond = (val[r] + (1.0f - css) / (float)(128 - i)) > 0.0f;
        rho += __popc(__ballot_sync(FULL, cond));
    }

    const int it = 128 - rho;
    const int Lt = it >> 2, rt = it & 3;
    const float sel = (rt == 0) ? cssr[0] : (rt == 1) ? cssr[1]
                    : (rt == 2) ? cssr[2] : cssr[3];
    const float css_t = __shfl_sync(FULL, sel, Lt);
    const float theta = (css_t - 1.0f) / (float)rho;

    float4 zo;
    zo.x = fmaxf(vorig[0] - theta, 0.0f);
    zo.y = fmaxf(vorig[1] - theta, 0.0f);
    zo.z = fmaxf(vorig[2] - theta, 0.0f);
    zo.w = fmaxf(vorig[3] - theta, 0.0f);
    *reinterpret_cast<float4*>(&zz[lane * 4]) = zo;
}

// ---------------------------------------------------------------------------
// Kernel 2: 512 threads, one CTA per TWO scenarios.
// Phase A: half-rows (t = wid*16 + lane&15, h = lane>>4), shfl_xor(16) combine.
// Phase B: quarter-column register cache (32 u64) + broadcast w.
// ---------------------------------------------------------------------------
__global__ __launch_bounds__(NTHREADS, 1)
void solver_kernel(const float* __restrict__ yhat_all,
                   const float* __restrict__ delta_p,
                   const float* __restrict__ gamma_p,
                   float* __restrict__ zout) {
    extern __shared__ char smem_raw[];
    SolverSmem* S = reinterpret_cast<SolverSmem*>(smem_raw);

    const int tid  = threadIdx.x;
    const int lane = tid & 31;
    const int wid  = tid >> 5;
    const int sA = blockIdx.x * 2;
    const int sB = sA + 1;
    const float delta = *delta_p;
    const float gamma = *gamma_p;

    for (int idx = tid; idx < N_OBS * N_Y; idx += NTHREADS) {
        const int t = idx >> 7;
        const int j = idx & 127;
        S->ep[t * EP_STRIDE + j] = g_ep[idx];
    }
    if (tid < N_Y) {
        S->zA[tid] = 1.0f / (float)N_Y;
        S->zB[tid] = 1.0f / (float)N_Y;
        S->yhA[tid] = yhat_all[sA * N_Y + tid];
        S->yhB[tid] = yhat_all[sB * N_Y + tid];
    }
    if (tid == 0)  { S->cA = 0.0f; S->etaA = 0.0f; S->lamA = 0.1f; }
    if (tid == 32) { S->cB = 0.0f; S->etaB = 0.0f; S->lamB = 0.1f; }
    __syncthreads();

    // ---- Phase A mapping: observation town, half hown ----
    const int town = wid * 16 + (lane & 15);     // 0..255
    const int hown = lane >> 4;                  // 0 or 1
    const ulonglong2* myrow =
        reinterpret_cast<const ulonglong2*>(&S->ep[town * EP_STRIDE + hown * 64]);

    // ---- Phase B mapping: output jown, t-quarter qt ----
    const int jown = tid & 127;
    const int qt   = tid >> 7;                   // 0..3
    const int tbase = qt * 64;
    unsigned long long ep2[32];                  // quarter column: 64 t's packed
#pragma unroll
    for (int q = 0; q < 32; q++)
        ep2[q] = pk2(S->ep[(tbase + 2 * q)     * EP_STRIDE + jown],
                     S->ep[(tbase + 2 * q + 1) * EP_STRIDE + jown]);

    for (int k = 0; k < NITERS; k++) {
        const float lr = 0.05f / sqrtf(1.0f + (float)k);
        const float cA = S->cA, etaA = S->etaA, lamA = S->lamA;
        const float cB = S->cB, etaB = S->etaB, lamB = S->lamB;

        // ---- Phase A: half-row dot products (LDS.128 + packed fma2) ----
        unsigned long long aA0 = 0, aA1 = 0, aB0 = 0, aB1 = 0;
        {
            const ulonglong2* zA2 =
                reinterpret_cast<const ulonglong2*>(&S->zA[hown * 64]);
            const ulonglong2* zB2 =
                reinterpret_cast<const ulonglong2*>(&S->zB[hown * 64]);
#pragma unroll
            for (int q = 0; q < 16; q++) {
                const ulonglong2 e  = myrow[q];
                const ulonglong2 za = zA2[q];
                const ulonglong2 zb = zB2[q];
                fma2(aA0, e.x, za.x);
                fma2(aA1, e.y, za.y);
                fma2(aB0, e.x, zb.x);
                fma2(aB1, e.y, zb.y);
            }
        }
        float rA = upk_sum(aA0) + upk_sum(aA1);
        float rB = upk_sum(aB0) + upk_sum(aB1);
        rA += __shfl_xor_sync(0xffffffffu, rA, 16);
        rB += __shfl_xor_sync(0xffffffffu, rB, 16);
        rA -= cA;
        rB -= cB;

        const float aAv = rA * rA - etaA;
        const float aBv = rB * rB - etaB;
        const float IA = (aAv > -lamA) ? 1.0f : ((aAv < -lamA) ? 0.0f : 0.5f);
        const float IB = (aBv > -lamB) ? 1.0f : ((aBv < -lamB) ? 0.0f : 0.5f);
        const float wAv = IA * 2.0f * rA * (1.0f / (float)N_OBS);
        const float wBv = IB * 2.0f * rB * (1.0f / (float)N_OBS);
        if (hown == 0) {
            S->wA[town] = wAv;
            S->wB[town] = wBv;
        }

        // Warp sums count each t twice (both halves) -> scale by 0.5.
        float sIA = IA, sWA = wAv, sIB = IB, sWB = wBv;
#pragma unroll
        for (int off = 16; off > 0; off >>= 1) {
            sIA += __shfl_down_sync(0xffffffffu, sIA, off);
            sWA += __shfl_down_sync(0xffffffffu, sWA, off);
            sIB += __shfl_down_sync(0xffffffffu, sIB, off);
            sWB += __shfl_down_sync(0xffffffffu, sWB, off);
        }
        if (lane == 0) {
            S->redIA[wid] = 0.5f * sIA; S->redWA[wid] = 0.5f * sWA;
            S->redIB[wid] = 0.5f * sIB; S->redWB[wid] = 0.5f * sWB;
        }
        __syncthreads();   // B1: w + per-warp reductions visible

        // ---- Phase B: partial g_z over this thread's t-quarter ----
        {
            const ulonglong2* wa2 = reinterpret_cast<const ulonglong2*>(&S->wA[tbase]);
            const ulonglong2* wb2 = reinterpret_cast<const ulonglong2*>(&S->wB[tbase]);
            unsigned long long pA0 = 0, pA1 = 0, pB0 = 0, pB1 = 0;
#pragma unroll
            for (int q = 0; q < 16; q++) {
                const ulonglong2 wa = wa2[q];
                const ulonglong2 wb = wb2[q];
                fma2(pA0, ep2[2 * q],     wa.x);
                fma2(pA1, ep2[2 * q + 1], wa.y);
                fma2(pB0, ep2[2 * q],     wb.x);
                fma2(pB1, ep2[2 * q + 1], wb.y);
            }
            S->partA[qt * N_Y + jown] = upk_sum(pA0) + upk_sum(pA1);
            S->partB[qt * N_Y + jown] = upk_sum(pB0) + upk_sum(pB1);
        }
        __syncthreads();   // B2: part visible

        // ---- B2->B3 window: projections (warps 0,1) + scalars (warp 2) ----
        if (wid == 0) {
            project_warp_blk(S->partA, S->yhA, S->zA, lr, gamma);
        } else if (wid == 1) {
            project_warp_blk(S->partB, S->yhB, S->zB, lr, gamma);
        } else if (wid == 2) {
            if (lane == 0) {
                float SI = 0.0f, SW = 0.0f;
#pragma unroll
                for (int i = 0; i < NWARPS; i++) { SI += S->redIA[i]; SW += S->redWA[i]; }
                S->cA   = cA + lr * SW;
                S->etaA = etaA - lr * (1.0f - SI * (1.0f / (float)N_OBS));
                S->lamA = fmaxf(lamA - lr * (delta - 1.0f + SI * (1.0f / (float)N_OBS)), 0.0f);
            } else if (lane == 1) {
                float SI = 0.0f, SW = 0.0f;
#pragma unroll
                for (int i = 0; i < NWARPS; i++) { SI += S->redIB[i]; SW += S->redWB[i]; }
                S->cB   = cB + lr * SW;
                S->etaB = etaB - lr * (1.0f - SI * (1.0f / (float)N_OBS));
                S->lamB = fmaxf(lamB - lr * (delta - 1.0f + SI * (1.0f / (float)N_OBS)), 0.0f);
            }
        }
        __syncthreads();   // B3: new z + scalars visible
    }

    if (tid < 128) {
        zout[sA * N_Y + tid] = S->zA[tid];
    } else if (tid < 256) {
        zout[sB * N_Y + (tid - 128)] = S->zB[tid - 128];
    }
}

// ---------------------------------------------------------------------------
extern "C" void kernel_launch(void* const* d_in, const int* in_sizes, int n_in,
                              void* d_out, int out_size) {
    const float* X     = (const float*)d_in[0];
    const float* Y     = (const float*)d_in[1];
    const float* W     = (const float*)d_in[2];
    const float* b     = (const float*)d_in[3];
    const float* delta = (const float*)d_in[4];
    const float* gamma = (const float*)d_in[5];

    float* out = (float*)d_out;
    float* zout = out;
    float* yhat;
    if (out_size >= 2 * N_OBS * N_Y) {
        yhat = out + N_OBS * N_Y;
    } else {
        void* p = nullptr;
        cudaGetSymbolAddress(&p, g_yhat_fallback);
        yhat = (float*)p;
    }

    static const size_t smem_bytes = sizeof(SolverSmem);
    cudaFuncSetAttribute(solver_kernel,
                         cudaFuncAttributeMaxDynamicSharedMemorySize,
                         (int)smem_bytes);

    prep_kernel<<<N_OBS, N_Y>>>(X, Y, W, b, yhat);
    solver_kernel<<<N_OBS / 2, NTHREADS, smem_bytes>>>(yhat, delta, gamma, zout);
}

// round 9
// speedup vs baseline: 1.1045x; 1.1045x over previous
#include <cuda_runtime.h>
#include <math.h>

#define N_OBS   256
#define N_Y     128
#define N_X     64
#define NITERS  150
#define NTHREADS 256
#define NWARPS   8
#define EP_STRIDE 132   // row-major ep stride: 528B/row -> conflict-free LDS.128

__device__ float g_ep[N_OBS * N_Y];             // ep row-major [t][j]
__device__ float g_yhat_fallback[N_OBS * N_Y];

struct SolverSmem {
    float ep[N_OBS * EP_STRIDE];                // 135168 B
    float zA[N_Y],  zB[N_Y];
    float yhA[N_Y], yhB[N_Y];
    unsigned long long wAs[N_OBS];              // splatted (w,w) pairs, scenario A
    unsigned long long wBs[N_OBS];              // scenario B
    float partA[NWARPS * N_Y];                  // per-warp g_z partials
    float partB[NWARPS * N_Y];
    float redIA[NWARPS], redWA[NWARPS], redIB[NWARPS], redWB[NWARPS];
    float cA, etaA, lamA;
    float cB, etaB, lamB;
};

// ---- packed f32x2 helpers (sm_103a) ---------------------------------------
__device__ __forceinline__ void fma2(unsigned long long& d,
                                     unsigned long long a,
                                     unsigned long long b) {
    asm("fma.rn.f32x2 %0, %1, %2, %0;" : "+l"(d) : "l"(a), "l"(b));
}
__device__ __forceinline__ unsigned long long pk2(float lo, float hi) {
    unsigned long long r;
    asm("mov.b64 %0, {%1, %2};" : "=l"(r) : "f"(lo), "f"(hi));
    return r;
}
__device__ __forceinline__ float upk_sum(unsigned long long v) {
    float lo, hi;
    asm("mov.b64 {%0, %1}, %2;" : "=f"(lo), "=f"(hi) : "l"(v));
    return lo + hi;
}
__device__ __forceinline__ float upk_lo(unsigned long long v) {
    float lo, hi;
    asm("mov.b64 {%0, %1}, %2;" : "=f"(lo), "=f"(hi) : "l"(v));
    return lo;
}
__device__ __forceinline__ float upk_hi(unsigned long long v) {
    float lo, hi;
    asm("mov.b64 {%0, %1}, %2;" : "=f"(lo), "=f"(hi) : "l"(v));
    return hi;
}

// ---------------------------------------------------------------------------
// Kernel 1: Y_hat = X @ W^T + b ; ep = Y - Y_hat (row-major)
// ---------------------------------------------------------------------------
__global__ void prep_kernel(const float* __restrict__ X,
                            const float* __restrict__ Y,
                            const float* __restrict__ W,
                            const float* __restrict__ b,
                            float* __restrict__ yhat_out) {
    __shared__ float Xs[N_X];
    __shared__ float Ws[N_Y * (N_X + 1)];
    const int t = blockIdx.x;
    const int i = threadIdx.x;

    if (i < N_X) Xs[i] = X[t * N_X + i];
    for (int idx = i; idx < N_Y * N_X; idx += blockDim.x) {
        int r = idx >> 6, cx = idx & 63;
        Ws[r * (N_X + 1) + cx] = W[idx];
    }
    __syncthreads();

    float acc = b[i];
#pragma unroll
    for (int x = 0; x < N_X; x++) acc += Xs[x] * Ws[i * (N_X + 1) + x];

    yhat_out[t * N_Y + i] = acc;
    g_ep[t * N_Y + i] = Y[t * N_Y + i] - acc;
}

// ---------------------------------------------------------------------------
// Block-layout warp-local simplex projection. Sums 8 per-warp partials,
// forms v = z - lr*(g - gamma*yh), projects onto simplex, writes z.
// Element i = lane*4 + r; strides 1,2 register-local; 15 SHFL levels.
// ---------------------------------------------------------------------------
__device__ __forceinline__ void cswap(float& a, float& b, bool asc) {
    const float lo = fminf(a, b), hi = fmaxf(a, b);
    a = asc ? lo : hi;
    b = asc ? hi : lo;
}

__device__ __forceinline__ void project_warp8(const float* __restrict__ part,
                                              const float* __restrict__ yh,
                                              float* __restrict__ zz,
                                              float lr, float gamma) {
    const unsigned FULL = 0xffffffffu;
    const int lane = threadIdx.x & 31;

    // Sum the 8 per-warp partials (conflict-free float4 reads).
    float g0 = 0.0f, g1 = 0.0f, g2 = 0.0f, g3 = 0.0f;
#pragma unroll
    for (int w = 0; w < NWARPS; w++) {
        const float4 p = *reinterpret_cast<const float4*>(&part[w * N_Y + lane * 4]);
        g0 += p.x; g1 += p.y; g2 += p.z; g3 += p.w;
    }
    const float4 yv = *reinterpret_cast<const float4*>(&yh[lane * 4]);
    const float4 zv = *reinterpret_cast<const float4*>(&zz[lane * 4]);

    float vorig[4], val[4];
    vorig[0] = zv.x - lr * (g0 - gamma * yv.x);
    vorig[1] = zv.y - lr * (g1 - gamma * yv.y);
    vorig[2] = zv.z - lr * (g2 - gamma * yv.z);
    vorig[3] = zv.w - lr * (g3 - gamma * yv.w);
#pragma unroll
    for (int r = 0; r < 4; r++) val[r] = vorig[r];

    // ---- bitonic ascending sort over i = lane*4 + r ----
    cswap(val[0], val[1], true);
    cswap(val[2], val[3], false);
    {
        const bool a = (lane & 1) == 0;
        cswap(val[0], val[2], a); cswap(val[1], val[3], a);
        cswap(val[0], val[1], a); cswap(val[2], val[3], a);
    }

#define SHFL_LEVEL(ls, asc) do {                                         \
        const bool _low = (lane & (ls)) == 0;                            \
        _Pragma("unroll")                                                \
        for (int r = 0; r < 4; r++) {                                    \
            const float pv = __shfl_xor_sync(FULL, val[r], (ls));        \
            val[r] = (_low == (asc)) ? fminf(val[r], pv)                 \
                                     : fmaxf(val[r], pv);                \
        }                                                                \
    } while (0)

#define REG_TAIL(asc) do {                                               \
        cswap(val[0], val[2], (asc)); cswap(val[1], val[3], (asc));      \
        cswap(val[0], val[1], (asc)); cswap(val[2], val[3], (asc));      \
    } while (0)

    { const bool a = (lane & 2)  == 0; SHFL_LEVEL(1, a); REG_TAIL(a); }
    { const bool a = (lane & 4)  == 0; SHFL_LEVEL(2, a); SHFL_LEVEL(1, a); REG_TAIL(a); }
    { const bool a = (lane & 8)  == 0; SHFL_LEVEL(4, a); SHFL_LEVEL(2, a); SHFL_LEVEL(1, a); REG_TAIL(a);}
    { const bool a = (lane & 16) == 0; SHFL_LEVEL(8, a); SHFL_LEVEL(4, a); SHFL_LEVEL(2, a);
      SHFL_LEVEL(1, a); REG_TAIL(a); }
    { SHFL_LEVEL(16, true); SHFL_LEVEL(8, true); SHFL_LEVEL(4, true); SHFL_LEVEL(2, true);
      SHFL_LEVEL(1, true); REG_TAIL(true); }

#undef SHFL_LEVEL
#undef REG_TAIL

    // ---- inclusive prefix sum over sorted values ----
    const float s0 = val[0];
    const float s1 = s0 + val[1];
    const float s2 = s1 + val[2];
    const float s3 = s2 + val[3];
    float incl = s3;
#pragma unroll
    for (int d = 1; d < 32; d <<= 1) {
        const float y = __shfl_up_sync(FULL, incl, d);
        if (lane >= d) incl += y;
    }
    const float prefix = incl - s3;
    const float Stot = __shfl_sync(FULL, incl, 31);
    const float P[4] = { s0 + prefix, s1 + prefix, s2 + prefix, s3 + prefix };

    int rho = 0;
    float cssr[4];
#pragma unroll
    for (int r = 0; r < 4; r++) {
        const int i = lane * 4 + r;
        const float css = Stot - P[r] + val[r];
        cssr[r] = css;
        const bool cond = (val[r] + (1.0f - css) / (float)(128 - i)) > 0.0f;
        rho += __popc(__ballot_sync(FULL, cond));
    }

    const int it = 128 - rho;
    const int Lt = it >> 2, rt = it & 3;
    const float sel = (rt == 0) ? cssr[0] : (rt == 1) ? cssr[1]
                    : (rt == 2) ? cssr[2] : cssr[3];
    const float css_t = __shfl_sync(FULL, sel, Lt);
    const float theta = (css_t - 1.0f) / (float)rho;

    float4 zo;
    zo.x = fmaxf(vorig[0] - theta, 0.0f);
    zo.y = fmaxf(vorig[1] - theta, 0.0f);
    zo.z = fmaxf(vorig[2] - theta, 0.0f);
    zo.w = fmaxf(vorig[3] - theta, 0.0f);
    *reinterpret_cast<float4*>(&zz[lane * 4]) = zo;
}

// ---------------------------------------------------------------------------
// Kernel 2: 256 threads, one CTA per TWO scenarios. TWO barriers per iter:
// Phase A (r_t, w_t) and Phase B (per-warp g_z partial over OWN warp's t's)
// run back-to-back with only a __syncwarp between them.
// ---------------------------------------------------------------------------
__global__ __launch_bounds__(NTHREADS, 1)
void solver_kernel(const float* __restrict__ yhat_all,
                   const float* __restrict__ delta_p,
                   const float* __restrict__ gamma_p,
                   float* __restrict__ zout) {
    extern __shared__ char smem_raw[];
    SolverSmem* S = reinterpret_cast<SolverSmem*>(smem_raw);

    const int tid  = threadIdx.x;
    const int lane = tid & 31;
    const int wid  = tid >> 5;
    const int sA = blockIdx.x * 2;
    const int sB = sA + 1;
    const float delta = *delta_p;
    const float gamma = *gamma_p;

    for (int idx = tid; idx < N_OBS * N_Y; idx += NTHREADS) {
        const int t = idx >> 7;
        const int j = idx & 127;
        S->ep[t * EP_STRIDE + j] = g_ep[idx];
    }
    if (tid < N_Y) {
        S->zA[tid] = 1.0f / (float)N_Y;
        S->zB[tid] = 1.0f / (float)N_Y;
        S->yhA[tid] = yhat_all[sA * N_Y + tid];
        S->yhB[tid] = yhat_all[sB * N_Y + tid];
    }
    if (tid == 0)  { S->cA = 0.0f; S->etaA = 0.0f; S->lamA = 0.1f; }
    if (tid == 32) { S->cB = 0.0f; S->etaB = 0.0f; S->lamB = 0.1f; }
    __syncthreads();

    // Phase A row pointer: thread t = tid owns observation tid.
    const ulonglong2* myrow =
        reinterpret_cast<const ulonglong2*>(&S->ep[tid * EP_STRIDE]);

    // Phase B register cache: lane holds ep[32*wid+tt][4*lane .. 4*lane+3]
    // for tt = 0..31 (own warp's observations), packed as 2 u64 per tt.
    unsigned long long epB[64];
#pragma unroll
    for (int tt = 0; tt < 32; tt++) {
        const float4 e =
            *reinterpret_cast<const float4*>(&S->ep[(32 * wid + tt) * EP_STRIDE + 4 * lane]);
        epB[2 * tt]     = pk2(e.x, e.y);
        epB[2 * tt + 1] = pk2(e.z, e.w);
    }

    for (int k = 0; k < NITERS; k++) {
        const float lr = 0.05f / sqrtf(1.0f + (float)k);
        const float cA = S->cA, etaA = S->etaA, lamA = S->lamA;
        const float cB = S->cB, etaB = S->etaB, lamB = S->lamB;

        // ---- Phase A: r_t = ep_t . z - c (LDS.128 rows, packed fma2) ----
        unsigned long long aA0 = 0, aA1 = 0, aB0 = 0, aB1 = 0;
        {
            const ulonglong2* zA2 = reinterpret_cast<const ulonglong2*>(S->zA);
            const ulonglong2* zB2 = reinterpret_cast<const ulonglong2*>(S->zB);
#pragma unroll
            for (int q = 0; q < N_Y / 4; q++) {
                const ulonglong2 e  = myrow[q];
                const ulonglong2 za = zA2[q];
                const ulonglong2 zb = zB2[q];
                fma2(aA0, e.x, za.x);
                fma2(aA1, e.y, za.y);
                fma2(aB0, e.x, zb.x);
                fma2(aB1, e.y, zb.y);
            }
        }
        const float rA = upk_sum(aA0) + upk_sum(aA1) - cA;
        const float rB = upk_sum(aB0) + upk_sum(aB1) - cB;

        const float aAv = rA * rA - etaA;
        const float aBv = rB * rB - etaB;
        const float IA = (aAv > -lamA) ? 1.0f : ((aAv < -lamA) ? 0.0f : 0.5f);
        const float IB = (aBv > -lamB) ? 1.0f : ((aBv < -lamB) ? 0.0f : 0.5f);
        const float wAv = IA * 2.0f * rA * (1.0f / (float)N_OBS);
        const float wBv = IB * 2.0f * rB * (1.0f / (float)N_OBS);

        // Splatted w pairs for Phase B broadcast (own warp reads them only).
        S->wAs[tid] = pk2(wAv, wAv);
        S->wBs[tid] = pk2(wBv, wBv);

        // Per-warp scalar reductions (consumed by warp 2 after B2).
        float sIA = IA, sWA = wAv, sIB = IB, sWB = wBv;
#pragma unroll
        for (int off = 16; off > 0; off >>= 1) {
            sIA += __shfl_down_sync(0xffffffffu, sIA, off);
            sWA += __shfl_down_sync(0xffffffffu, sWA, off);
            sIB += __shfl_down_sync(0xffffffffu, sIB, off);
            sWB += __shfl_down_sync(0xffffffffu, sWB, off);
        }
        if (lane == 0) {
            S->redIA[wid] = sIA; S->redWA[wid] = sWA;
            S->redIB[wid] = sIB; S->redWB[wid] = sWB;
        }
        __syncwarp();   // own-warp wAs/wBs visible (no block barrier!)

        // ---- Phase B: per-warp partial g_z over OWN warp's 32 t's ----
        {
            unsigned long long gA0 = 0, gA1 = 0, gB0 = 0, gB1 = 0;
            const unsigned long long* wa = &S->wAs[32 * wid];
            const unsigned long long* wb = &S->wBs[32 * wid];
#pragma unroll
            for (int tt = 0; tt < 32; tt++) {
                const unsigned long long pa = wa[tt];   // LDS.64 broadcast
                const unsigned long long pb = wb[tt];
                fma2(gA0, epB[2 * tt],     pa);
                fma2(gA1, epB[2 * tt + 1], pa);
                fma2(gB0, epB[2 * tt],     pb);
                fma2(gB1, epB[2 * tt + 1], pb);
            }
            float4 oa, ob;
            oa.x = upk_lo(gA0); oa.y = upk_hi(gA0);
            oa.z = upk_lo(gA1); oa.w = upk_hi(gA1);
            ob.x = upk_lo(gB0); ob.y = upk_hi(gB0);
            ob.z = upk_lo(gB1); ob.w = upk_hi(gB1);
            *reinterpret_cast<float4*>(&S->partA[wid * N_Y + 4 * lane]) = oa;
            *reinterpret_cast<float4*>(&S->partB[wid * N_Y + 4 * lane]) = ob;
        }
        __syncthreads();   // B2: partials + reductions visible

        // ---- B2->B3 window: projections (warps 0,1) + scalars (warp 2) ----
        if (wid == 0) {
            project_warp8(S->partA, S->yhA, S->zA, lr, gamma);
        } else if (wid == 1) {
            project_warp8(S->partB, S->yhB, S->zB, lr, gamma);
        } else if (wid == 2) {
            if (lane == 0) {
                float SI = 0.0f, SW = 0.0f;
#pragma unroll
                for (int i = 0; i < NWARPS; i++) { SI += S->redIA[i]; SW += S->redWA[i]; }
                S->cA   = cA + lr * SW;
                S->etaA = etaA - lr * (1.0f - SI * (1.0f / (float)N_OBS));
                S->lamA = fmaxf(lamA - lr * (delta - 1.0f + SI * (1.0f / (float)N_OBS)), 0.0f);
            } else if (lane == 1) {
                float SI = 0.0f, SW = 0.0f;
#pragma unroll
                for (int i = 0; i < NWARPS; i++) { SI += S->redIB[i]; SW += S->redWB[i]; }
                S->cB   = cB + lr * SW;
                S->etaB = etaB - lr * (1.0f - SI * (1.0f / (float)N_OBS));
                S->lamB = fmaxf(lamB - lr * (delta - 1.0f + SI * (1.0f / (float)N_OBS)), 0.0f);
            }
        }
        __syncthreads();   // B3: new z + scalars visible
    }

    if (tid < 128) {
        zout[sA * N_Y + tid] = S->zA[tid];
    } else {
        zout[sB * N_Y + (tid - 128)] = S->zB[tid - 128];
    }
}

// ---------------------------------------------------------------------------
extern "C" void kernel_launch(void* const* d_in, const int* in_sizes, int n_in,
                              void* d_out, int out_size) {
    const float* X     = (const float*)d_in[0];
    const float* Y     = (const float*)d_in[1];
    const float* W     = (const float*)d_in[2];
    const float* b     = (const float*)d_in[3];
    const float* delta = (const float*)d_in[4];
    const float* gamma = (const float*)d_in[5];

    float* out = (float*)d_out;
    float* zout = out;
    float* yhat;
    if (out_size >= 2 * N_OBS * N_Y) {
        yhat = out + N_OBS * N_Y;
    } else {
        void* p = nullptr;
        cudaGetSymbolAddress(&p, g_yhat_fallback);
        yhat = (float*)p;
    }

    static const size_t smem_bytes = sizeof(SolverSmem);
    cudaFuncSetAttribute(solver_kernel,
                         cudaFuncAttributeMaxDynamicSharedMemorySize,
                         (int)smem_bytes);

    prep_kernel<<<N_OBS, N_Y>>>(X, Y, W, b, yhat);
    solver_kernel<<<N_OBS / 2, NTHREADS, smem_bytes>>>(yhat, delta, gamma, zout);
}

// round 10
// speedup vs baseline: 1.3807x; 1.2501x over previous
#include <cuda_runtime.h>
#include <math.h>

#define N_OBS   256
#define N_Y     128
#define N_X     64
#define NITERS  150
#define NTHREADS 256
#define NWARPS   8

__device__ float g_ep[N_OBS * N_Y];             // ep row-major [t][j]
__device__ float g_yhat_fallback[N_OBS * N_Y];

// ---- packed f32x2 helpers (sm_103a) ---------------------------------------
typedef unsigned long long u64;
__device__ __forceinline__ void fma2(u64& d, u64 a, u64 b) {
    asm("fma.rn.f32x2 %0, %1, %2, %0;" : "+l"(d) : "l"(a), "l"(b));
}
__device__ __forceinline__ void add2(u64& d, u64 a) {
    asm("add.rn.f32x2 %0, %0, %1;" : "+l"(d) : "l"(a));
}
__device__ __forceinline__ u64 pk2(float lo, float hi) {
    u64 r;
    asm("mov.b64 %0, {%1, %2};" : "=l"(r) : "f"(lo), "f"(hi));
    return r;
}
__device__ __forceinline__ float upk_lo(u64 v) {
    float lo, hi; asm("mov.b64 {%0, %1}, %2;" : "=f"(lo), "=f"(hi) : "l"(v)); return lo;
}
__device__ __forceinline__ float upk_hi(u64 v) {
    float lo, hi; asm("mov.b64 {%0, %1}, %2;" : "=f"(lo), "=f"(hi) : "l"(v)); return hi;
}
__device__ __forceinline__ float upk_sum(u64 v) {
    float lo, hi; asm("mov.b64 {%0, %1}, %2;" : "=f"(lo), "=f"(hi) : "l"(v)); return lo + hi;
}

// ---------------------------------------------------------------------------
// Kernel 1: Y_hat = X @ W^T + b ; ep = Y - Y_hat (row-major)
// ---------------------------------------------------------------------------
__global__ void prep_kernel(const float* __restrict__ X,
                            const float* __restrict__ Y,
                            const float* __restrict__ W,
                            const float* __restrict__ b,
                            float* __restrict__ yhat_out) {
    __shared__ float Xs[N_X];
    __shared__ float Ws[N_Y * (N_X + 1)];
    const int t = blockIdx.x;
    const int i = threadIdx.x;

    if (i < N_X) Xs[i] = X[t * N_X + i];
    for (int idx = i; idx < N_Y * N_X; idx += blockDim.x) {
        int r = idx >> 6, cx = idx & 63;
        Ws[r * (N_X + 1) + cx] = W[idx];
    }
    __syncthreads();

    float acc = b[i];
#pragma unroll
    for (int x = 0; x < N_X; x++) acc += Xs[x] * Ws[i * (N_X + 1) + x];

    yhat_out[t * N_Y + i] = acc;
    g_ep[t * N_Y + i] = Y[t * N_Y + i] - acc;
}

// ---------------------------------------------------------------------------
// Block-layout warp-local simplex projection: sums 8 per-warp partials,
// v = z - lr*(g - gamma*yh), z = proj_simplex(v). i = lane*4 + r.
// ---------------------------------------------------------------------------
__device__ __forceinline__ void cswap(float& a, float& b, bool asc) {
    const float lo = fminf(a, b), hi = fmaxf(a, b);
    a = asc ? lo : hi;
    b = asc ? hi : lo;
}

__device__ __forceinline__ void project_warp8(const float* __restrict__ part,
                                              const float* __restrict__ yh,
                                              float* __restrict__ zz,
                                              float lr, float gamma) {
    const unsigned FULL = 0xffffffffu;
    const int lane = threadIdx.x & 31;

    float g0 = 0.0f, g1 = 0.0f, g2 = 0.0f, g3 = 0.0f;
#pragma unroll
    for (int w = 0; w < NWARPS; w++) {
        const float4 p = *reinterpret_cast<const float4*>(&part[w * N_Y + lane * 4]);
        g0 += p.x; g1 += p.y; g2 += p.z; g3 += p.w;
    }
    const float4 yv = *reinterpret_cast<const float4*>(&yh[lane * 4]);
    const float4 zv = *reinterpret_cast<const float4*>(&zz[lane * 4]);

    float vorig[4], val[4];
    vorig[0] = zv.x - lr * (g0 - gamma * yv.x);
    vorig[1] = zv.y - lr * (g1 - gamma * yv.y);
    vorig[2] = zv.z - lr * (g2 - gamma * yv.z);
    vorig[3] = zv.w - lr * (g3 - gamma * yv.w);
#pragma unroll
    for (int r = 0; r < 4; r++) val[r] = vorig[r];

    cswap(val[0], val[1], true);
    cswap(val[2], val[3], false);
    {
        const bool a = (lane & 1) == 0;
        cswap(val[0], val[2], a); cswap(val[1], val[3], a);
        cswap(val[0], val[1], a); cswap(val[2], val[3], a);
    }

#define SHFL_LEVEL(ls, asc) do {                                         \
        const bool _low = (lane & (ls)) == 0;                            \
        _Pragma("unroll")                                                \
        for (int r = 0; r < 4; r++) {                                    \
            const float pv = __shfl_xor_sync(FULL, val[r], (ls));        \
            val[r] = (_low == (asc)) ? fminf(val[r], pv)                 \
                                     : fmaxf(val[r], pv);                \
        }                                                                \
    } while (0)

#define REG_TAIL(asc) do {                                               \
        cswap(val[0], val[2], (asc)); cswap(val[1], val[3], (asc));      \
        cswap(val[0], val[1], (asc)); cswap(val[2], val[3], (asc));      \
    } while (0)

    { const bool a = (lane & 2)  == 0; SHFL_LEVEL(1, a); REG_TAIL(a); }
    { const bool a = (lane & 4)  == 0; SHFL_LEVEL(2, a); SHFL_LEVEL(1, a); REG_TAIL(a); }
    { const bool a = (lane & 8)  == 0; SHFL_LEVEL(4, a); SHFL_LEVEL(2, a); SHFL_LEVEL(1, a); REG_TAIL(a);}
    { const bool a = (lane & 16) == 0; SHFL_LEVEL(8, a); SHFL_LEVEL(4, a); SHFL_LEVEL(2, a);
      SHFL_LEVEL(1, a); REG_TAIL(a); }
    { SHFL_LEVEL(16, true); SHFL_LEVEL(8, true); SHFL_LEVEL(4, true); SHFL_LEVEL(2, true);
      SHFL_LEVEL(1, true); REG_TAIL(true); }

#undef SHFL_LEVEL
#undef REG_TAIL

    const float s0 = val[0];
    const float s1 = s0 + val[1];
    const float s2 = s1 + val[2];
    const float s3 = s2 + val[3];
    float incl = s3;
#pragma unroll
    for (int d = 1; d < 32; d <<= 1) {
        const float y = __shfl_up_sync(FULL, incl, d);
        if (lane >= d) incl += y;
    }
    const float prefix = incl - s3;
    const float Stot = __shfl_sync(FULL, incl, 31);
    const float P[4] = { s0 + prefix, s1 + prefix, s2 + prefix, s3 + prefix };

    int rho = 0;
    float cssr[4];
#pragma unroll
    for (int r = 0; r < 4; r++) {
        const int i = lane * 4 + r;
        const float css = Stot - P[r] + val[r];
        cssr[r] = css;
        const bool cond = (val[r] + (1.0f - css) / (float)(128 - i)) > 0.0f;
        rho += __popc(__ballot_sync(FULL, cond));
    }

    const int it = 128 - rho;
    const int Lt = it >> 2, rt = it & 3;
    const float sel = (rt == 0) ? cssr[0] : (rt == 1) ? cssr[1]
                    : (rt == 2) ? cssr[2] : cssr[3];
    const float css_t = __shfl_sync(FULL, sel, Lt);
    const float theta = (css_t - 1.0f) / (float)rho;

    float4 zo;
    zo.x = fmaxf(vorig[0] - theta, 0.0f);
    zo.y = fmaxf(vorig[1] - theta, 0.0f);
    zo.z = fmaxf(vorig[2] - theta, 0.0f);
    zo.w = fmaxf(vorig[3] - theta, 0.0f);
    *reinterpret_cast<float4*>(&zz[lane * 4]) = zo;
}

// ---------------------------------------------------------------------------
// Kernel 2: 256 threads, one CTA per TWO scenarios, FULLY register-resident
// matrix. Phase A: per-lane 4-wide partials + log-halving transpose-reduce
// (31 shfl) -> lane L holds r_t for t=32*wid+L. Phase B: shfl w + fma2.
// Only 2 block barriers per iteration; near-zero SMEM crossbar traffic.
// ---------------------------------------------------------------------------
__global__ __launch_bounds__(NTHREADS, 1)
void solver_kernel(const float* __restrict__ yhat_all,
                   const float* __restrict__ delta_p,
                   const float* __restrict__ gamma_p,
                   float* __restrict__ zout) {
    __shared__ float zA[N_Y], zB[N_Y];
    __shared__ float yhA[N_Y], yhB[N_Y];
    __shared__ float partA[NWARPS * N_Y], partB[NWARPS * N_Y];
    __shared__ float redIA[NWARPS], redWA[NWARPS], redIB[NWARPS], redWB[NWARPS];
    __shared__ float cAs, etaAs, lamAs, cBs, etaBs, lamBs;

    const int tid  = threadIdx.x;
    const int lane = tid & 31;
    const int wid  = tid >> 5;
    const int sA = blockIdx.x * 2;
    const int sB = sA + 1;
    const float delta = *delta_p;
    const float gamma = *gamma_p;
    const unsigned FULL = 0xffffffffu;

    if (tid < N_Y) {
        zA[tid] = 1.0f / (float)N_Y;
        zB[tid] = 1.0f / (float)N_Y;
        yhA[tid] = yhat_all[sA * N_Y + tid];
        yhB[tid] = yhat_all[sB * N_Y + tid];
    }
    if (tid == 0) { cAs = 0.0f; etaAs = 0.0f; lamAs = 0.1f;
                    cBs = 0.0f; etaBs = 0.0f; lamBs = 0.1f; }

    // Register matrix cache straight from global (coalesced float4 rows):
    // epB[2*tt]   = (ep[32*wid+tt][4*lane],   ep[.][4*lane+1])
    // epB[2*tt+1] = (ep[32*wid+tt][4*lane+2], ep[.][4*lane+3])
    u64 epB[64];
#pragma unroll
    for (int tt = 0; tt < 32; tt++) {
        const float4 e = *reinterpret_cast<const float4*>(
            &g_ep[(32 * wid + tt) * N_Y + 4 * lane]);
        epB[2 * tt]     = pk2(e.x, e.y);
        epB[2 * tt + 1] = pk2(e.z, e.w);
    }
    __syncthreads();

    for (int k = 0; k < NITERS; k++) {
        const float lr = 0.05f / sqrtf(1.0f + (float)k);
        const float cA = cAs, etaA = etaAs, lamA = lamAs;
        const float cB = cBs, etaB = etaBs, lamB = lamBs;

        // ---- Phase A: packed partial dots, then transpose-reduce ----
        const float4 zva = *reinterpret_cast<const float4*>(&zA[4 * lane]);
        const float4 zvb = *reinterpret_cast<const float4*>(&zB[4 * lane]);
        const u64 zA0 = pk2(zva.x, zva.y), zA1 = pk2(zva.z, zva.w);
        const u64 zB0 = pk2(zvb.x, zvb.y), zB1 = pk2(zvb.z, zvb.w);

        u64 p[32];   // packed (partialA, partialB) per tt
#pragma unroll
        for (int tt = 0; tt < 32; tt++) {
            u64 a = 0, b = 0;
            fma2(a, epB[2 * tt],     zA0);
            fma2(a, epB[2 * tt + 1], zA1);
            fma2(b, epB[2 * tt],     zB0);
            fma2(b, epB[2 * tt + 1], zB1);
            p[tt] = pk2(upk_sum(a), upk_sum(b));
        }

        // log-halving transpose-reduce: lane L ends with sum over lanes for tt=L
#pragma unroll
        for (int d = 16; d >= 1; d >>= 1) {
            const bool hi = (lane & d) != 0;
#pragma unroll
            for (int i = 0; i < d; i++) {
                u64 keep = hi ? p[i + d] : p[i];
                u64 send = hi ? p[i] : p[i + d];
                const u64 recv = __shfl_xor_sync(FULL, send, d);
                add2(keep, recv);
                p[i] = keep;
            }
        }
        const float rA = upk_lo(p[0]) - cA;   // r for t = 32*wid + lane
        const float rB = upk_hi(p[0]) - cB;

        const float aAv = rA * rA - etaA;
        const float aBv = rB * rB - etaB;
        const float IA = (aAv > -lamA) ? 1.0f : ((aAv < -lamA) ? 0.0f : 0.5f);
        const float IB = (aBv > -lamB) ? 1.0f : ((aBv < -lamB) ? 0.0f : 0.5f);
        const float wAv = IA * 2.0f * rA * (1.0f / (float)N_OBS);
        const float wBv = IB * 2.0f * rB * (1.0f / (float)N_OBS);

        // Per-warp scalar reductions (packed butterfly)
        {
            u64 sI = pk2(IA, IB);
            u64 sW = pk2(wAv, wBv);
#pragma unroll
            for (int d = 16; d >= 1; d >>= 1) {
                add2(sI, __shfl_xor_sync(FULL, sI, d));
                add2(sW, __shfl_xor_sync(FULL, sW, d));
            }
            if (lane == 0) {
                redIA[wid] = upk_lo(sI); redIB[wid] = upk_hi(sI);
                redWA[wid] = upk_lo(sW); redWB[wid] = upk_hi(sW);
            }
        }

        // ---- Phase B: per-warp partial g_z over own 32 t's (w via shfl) ----
        {
            u64 gA0 = 0, gA1 = 0, gB0 = 0, gB1 = 0;
#pragma unroll
            for (int tt = 0; tt < 32; tt++) {
                const float wa = __shfl_sync(FULL, wAv, tt);
                const float wb = __shfl_sync(FULL, wBv, tt);
                const u64 wap = pk2(wa, wa);
                const u64 wbp = pk2(wb, wb);
                fma2(gA0, epB[2 * tt],     wap);
                fma2(gA1, epB[2 * tt + 1], wap);
                fma2(gB0, epB[2 * tt],     wbp);
                fma2(gB1, epB[2 * tt + 1], wbp);
            }
            float4 oa, ob;
            oa.x = upk_lo(gA0); oa.y = upk_hi(gA0);
            oa.z = upk_lo(gA1); oa.w = upk_hi(gA1);
            ob.x = upk_lo(gB0); ob.y = upk_hi(gB0);
            ob.z = upk_lo(gB1); ob.w = upk_hi(gB1);
            *reinterpret_cast<float4*>(&partA[wid * N_Y + 4 * lane]) = oa;
            *reinterpret_cast<float4*>(&partB[wid * N_Y + 4 * lane]) = ob;
        }
        __syncthreads();   // B2: partials + reductions visible

        // ---- window: projections (warps 0,1) + scalar updates (warp 2) ----
        if (wid == 0) {
            project_warp8(partA, yhA, zA, lr, gamma);
        } else if (wid == 1) {
            project_warp8(partB, yhB, zB, lr, gamma);
        } else if (wid == 2) {
            if (lane == 0) {
                float SI = 0.0f, SW = 0.0f;
#pragma unroll
                for (int i = 0; i < NWARPS; i++) { SI += redIA[i]; SW += redWA[i]; }
                cAs   = cA + lr * SW;
                etaAs = etaA - lr * (1.0f - SI * (1.0f / (float)N_OBS));
                lamAs = fmaxf(lamA - lr * (delta - 1.0f + SI * (1.0f / (float)N_OBS)), 0.0f);
            } else if (lane == 1) {
                float SI = 0.0f, SW = 0.0f;
#pragma unroll
                for (int i = 0; i < NWARPS; i++) { SI += redIB[i]; SW += redWB[i]; }
                cBs   = cB + lr * SW;
                etaBs = etaB - lr * (1.0f - SI * (1.0f / (float)N_OBS));
                lamBs = fmaxf(lamB - lr * (delta - 1.0f + SI * (1.0f / (float)N_OBS)), 0.0f);
            }
        }
        __syncthreads();   // B3: new z + scalars visible
    }

    if (tid < 128) {
        zout[sA * N_Y + tid] = zA[tid];
    } else {
        zout[sB * N_Y + (tid - 128)] = zB[tid - 128];
    }
}

// ---------------------------------------------------------------------------
extern "C" void kernel_launch(void* const* d_in, const int* in_sizes, int n_in,
                              void* d_out, int out_size) {
    const float* X     = (const float*)d_in[0];
    const float* Y     = (const float*)d_in[1];
    const float* W     = (const float*)d_in[2];
    const float* b     = (const float*)d_in[3];
    const float* delta = (const float*)d_in[4];
    const float* gamma = (const float*)d_in[5];

    float* out = (float*)d_out;
    float* zout = out;
    float* yhat;
    if (out_size >= 2 * N_OBS * N_Y) {
        yhat = out + N_OBS * N_Y;
    } else {
        void* p = nullptr;
        cudaGetSymbolAddress(&p, g_yhat_fallback);
        yhat = (float*)p;
    }

    prep_kernel<<<N_OBS, N_Y>>>(X, Y, W, b, yhat);
    solver_kernel<<<N_OBS / 2, NTHREADS>>>(yhat, delta, gamma, zout);
}